// round 5
// baseline (speedup 1.0000x reference)
#include <cuda_runtime.h>
#include <cstddef>

// Problem constants (fixed by the dataset)
#define E_DIM 128
#define S_DIM 64
#define P_DIM 256
#define B_DIM 4096

// ---------------------------------------------------------------------------
// Persistent device scratch for the path metadata, sorted by output segment.
// (No cudaMalloc allowed; __device__ globals are the sanctioned scratch.)
// ---------------------------------------------------------------------------
__device__ int   d_seg_start[S_DIM + 1];   // segment s3 spans [seg_start[s3], seg_start[s3+1])
__device__ int   d_path_i1[P_DIM];         // i1 * E  (pre-scaled row offset into x)
__device__ int   d_path_i2[P_DIM];         // i2 * E
__device__ float d_path_c [P_DIM];         // path coefficient

// ---------------------------------------------------------------------------
// Prep kernel: deterministic stable counting-sort of the 256 paths by i3.
// One block, 256 threads; runs every launch (graph-replay safe, ~2 us).
// ---------------------------------------------------------------------------
__global__ void prep_paths_kernel(const float* __restrict__ path_coeff,
                                  const int*   __restrict__ path_idx)
{
    __shared__ int s_i3[P_DIM];
    __shared__ int s_cnt[S_DIM + 1];

    const int t = threadIdx.x;               // 0..255
    const int i1 = path_idx[t * 3 + 0];
    const int i2 = path_idx[t * 3 + 1];
    const int i3 = path_idx[t * 3 + 2];
    s_i3[t] = i3;
    if (t <= S_DIM) s_cnt[t] = 0;
    __syncthreads();

    atomicAdd(&s_cnt[i3 + 1], 1);
    __syncthreads();

    if (t == 0) {                            // inclusive prefix over 65 ints
        int acc = 0;
        #pragma unroll
        for (int i = 0; i <= S_DIM; i++) { acc += s_cnt[i]; s_cnt[i] = acc; }
    }
    __syncthreads();

    if (t <= S_DIM) d_seg_start[t] = s_cnt[t];

    // Stable rank within my segment: count earlier paths with the same i3.
    int rank = 0;
    for (int j = 0; j < t; j++) rank += (s_i3[j] == i3) ? 1 : 0;
    const int pos = s_cnt[i3] + rank;

    d_path_i1[pos] = i1 * E_DIM;
    d_path_i2[pos] = i2 * E_DIM;
    d_path_c [pos] = path_coeff[t];
}

// ---------------------------------------------------------------------------
// Main kernel: one CTA per batch row b. 128 threads, thread t owns e-lane t.
// x-row and y-row staged in shared (32 KB each, float4 coalesced loads).
// Paths are grouped by output segment, so the accumulator is a register.
// ---------------------------------------------------------------------------
#define ROW_FLOATS (S_DIM * E_DIM)          // 8192 floats = 32 KB
#define SMEM_FLOATS (2 * ROW_FLOATS + (S_DIM + 1) + 3 * P_DIM)
#define SMEM_BYTES  (SMEM_FLOATS * 4)

__global__ __launch_bounds__(128, 3)
void seg_poly_kernel(const float* __restrict__ x_table,
                     const float* __restrict__ y,
                     const int*   __restrict__ x_idx,
                     float*       __restrict__ out)
{
    extern __shared__ float smem[];
    float* sx   = smem;                       // [ROW_FLOATS]
    float* sy   = smem + ROW_FLOATS;          // [ROW_FLOATS]
    int*   sseg = (int*)  (smem + 2 * ROW_FLOATS);            // [S+1]
    int*   si1  = sseg + (S_DIM + 1);                         // [P]
    int*   si2  = si1 + P_DIM;                                // [P]
    float* sc   = (float*)(si2 + P_DIM);                      // [P]

    const int b = blockIdx.x;
    const int t = threadIdx.x;                // 0..127

    // Stage x-row (gathered) and y-row into shared with float4 loads.
    const size_t xrow = (size_t)x_idx[b] * ROW_FLOATS;
    const float4* xr = (const float4*)(x_table + xrow);
    const float4* yr = (const float4*)(y + (size_t)b * ROW_FLOATS);
    float4* sx4 = (float4*)sx;
    float4* sy4 = (float4*)sy;
    #pragma unroll
    for (int i = 0; i < (ROW_FLOATS / 4) / 128; i++) {        // 16 iters
        sx4[t + i * 128] = xr[t + i * 128];
        sy4[t + i * 128] = yr[t + i * 128];
    }

    // Stage path metadata.
    if (t <= S_DIM) sseg[t] = d_seg_start[t];
    #pragma unroll
    for (int i = t; i < P_DIM; i += 128) {
        si1[i] = d_path_i1[i];
        si2[i] = d_path_i2[i];
        sc [i] = d_path_c [i];
    }
    __syncthreads();

    // Walk output segments in order; accumulator lives in a register.
    float* orow = out + (size_t)b * ROW_FLOATS + t;
    #pragma unroll 4
    for (int s3 = 0; s3 < S_DIM; s3++) {
        const int beg = sseg[s3];
        const int end = sseg[s3 + 1];
        float acc = 0.0f;
        for (int j = beg; j < end; j++) {
            acc = fmaf(sc[j] * sx[si1[j] + t], sy[si2[j] + t], acc);
        }
        orow[(size_t)s3 * E_DIM] = acc;       // empty segments write 0
    }
}

// ---------------------------------------------------------------------------
// Launch wrapper. Inputs (metadata order):
//   0: x_table  f32 [N, S*E]
//   1: y        f32 [B, S*E]
//   2: path_coeff f32 [P]
//   3: x_idx    i32 [B]
//   4: path_idx i32 [P, 3]
// Output: f32 [B, S*E]
// ---------------------------------------------------------------------------
extern "C" void kernel_launch(void* const* d_in, const int* in_sizes, int n_in,
                              void* d_out, int out_size)
{
    const float* x_table    = (const float*)d_in[0];
    const float* y          = (const float*)d_in[1];
    const float* path_coeff = (const float*)d_in[2];
    const int*   x_idx      = (const int*)  d_in[3];
    const int*   path_idx   = (const int*)  d_in[4];
    float*       out        = (float*)d_out;

    (void)in_sizes; (void)n_in; (void)out_size;

    static bool attr_set = false;
    if (!attr_set) {
        cudaFuncSetAttribute(seg_poly_kernel,
                             cudaFuncAttributeMaxDynamicSharedMemorySize,
                             SMEM_BYTES);
        attr_set = true;
    }

    prep_paths_kernel<<<1, P_DIM>>>(path_coeff, path_idx);
    seg_poly_kernel<<<B_DIM, 128, SMEM_BYTES>>>(x_table, y, x_idx, out);
}

// round 6
// speedup vs baseline: 2.1539x; 2.1539x over previous
#include <cuda_runtime.h>
#include <cstdint>
#include <cstddef>

// Problem constants (fixed by the dataset)
#define E_DIM 128
#define S_DIM 64
#define P_DIM 256
#define B_DIM 4096
#define ROW_FLOATS (S_DIM * E_DIM)          // 8192 floats = 32 KB
#define ROW_BYTES  (ROW_FLOATS * 4)

// ---------------------------------------------------------------------------
// Persistent device scratch: paths sorted by output segment i3.
// meta.x = (i1*32)<<16 | (i2*32)   (float4-unit row offsets, each <= 2016)
// meta.y = bitcast(path coefficient)
// ---------------------------------------------------------------------------
__device__ int  d_seg_start[S_DIM + 1];
__device__ int2 d_meta[P_DIM];

// ---------------------------------------------------------------------------
// Prep: deterministic stable counting-sort of 256 paths by i3 (~2 us).
// ---------------------------------------------------------------------------
__global__ void prep_paths_kernel(const float* __restrict__ path_coeff,
                                  const int*   __restrict__ path_idx)
{
    __shared__ int s_i3[P_DIM];
    __shared__ int s_cnt[S_DIM + 1];

    const int t  = threadIdx.x;              // 0..255
    const int i1 = path_idx[t * 3 + 0];
    const int i2 = path_idx[t * 3 + 1];
    const int i3 = path_idx[t * 3 + 2];
    s_i3[t] = i3;
    if (t <= S_DIM) s_cnt[t] = 0;
    __syncthreads();

    atomicAdd(&s_cnt[i3 + 1], 1);
    __syncthreads();

    if (t == 0) {
        int acc = 0;
        #pragma unroll
        for (int i = 0; i <= S_DIM; i++) { acc += s_cnt[i]; s_cnt[i] = acc; }
    }
    __syncthreads();

    if (t <= S_DIM) d_seg_start[t] = s_cnt[t];

    int rank = 0;                            // stable rank within segment
    for (int j = 0; j < t; j++) rank += (s_i3[j] == i3) ? 1 : 0;
    const int pos = s_cnt[i3] + rank;

    d_meta[pos] = make_int2(((i1 * (E_DIM / 4)) << 16) | (i2 * (E_DIM / 4)),
                            __float_as_int(path_coeff[t]));
}

// ---------------------------------------------------------------------------
// Shared-memory layout (dynamic):
//   [0,8)        mbarrier
//   [16,276)     seg_start[65]
//   [280,2328)   meta int2[256]
//   [2432,35200) sx  (32 KB, x-row)
//   [35200,67968) sy (32 KB, y-row)
// ---------------------------------------------------------------------------
#define OFF_MBAR 0
#define OFF_SEG  16
#define OFF_META 280
#define OFF_SX   2432
#define OFF_SY   (OFF_SX + ROW_BYTES)
#define SMEM_BYTES (OFF_SY + ROW_BYTES)

__device__ __forceinline__ uint32_t smem_u32(const void* p) {
    uint32_t a;
    asm("{ .reg .u64 t; cvta.to.shared.u64 t, %1; cvt.u32.u64 %0, t; }"
        : "=r"(a) : "l"(p));
    return a;
}

__global__ __launch_bounds__(128, 3)
void seg_poly_kernel(const float* __restrict__ x_table,
                     const float* __restrict__ y,
                     const int*   __restrict__ x_idx,
                     float*       __restrict__ out)
{
    extern __shared__ char smem[];
    int*          sseg  = (int*)  (smem + OFF_SEG);
    int2*         smeta = (int2*) (smem + OFF_META);
    const float4* sx4   = (const float4*)(smem + OFF_SX);
    const float4* sy4   = (const float4*)(smem + OFF_SY);

    const int b    = blockIdx.x;
    const int t    = threadIdx.x;            // 0..127
    const int warp = t >> 5;
    const int lane = t & 31;

    const uint32_t mbar = smem_u32(smem + OFF_MBAR);

    // --- init mbarrier, then kick off the two 32 KB bulk copies ------------
    if (t == 0) {
        asm volatile("mbarrier.init.shared.b64 [%0], 1;" :: "r"(mbar) : "memory");
    }
    __syncthreads();

    if (t == 0) {
        asm volatile("mbarrier.arrive.expect_tx.shared.b64 _, [%0], %1;"
                     :: "r"(mbar), "r"(2 * ROW_BYTES) : "memory");
        const char* xsrc = (const char*)(x_table + (size_t)x_idx[b] * ROW_FLOATS);
        const char* ysrc = (const char*)(y       + (size_t)b        * ROW_FLOATS);
        asm volatile(
            "cp.async.bulk.shared::cta.global.mbarrier::complete_tx::bytes "
            "[%0], [%1], %2, [%3];"
            :: "r"(smem_u32(smem + OFF_SX)), "l"(xsrc), "r"(ROW_BYTES), "r"(mbar)
            : "memory");
        asm volatile(
            "cp.async.bulk.shared::cta.global.mbarrier::complete_tx::bytes "
            "[%0], [%1], %2, [%3];"
            :: "r"(smem_u32(smem + OFF_SY)), "l"(ysrc), "r"(ROW_BYTES), "r"(mbar)
            : "memory");
    }

    // --- overlap: stage path metadata while bulk copies fly ----------------
    if (t <= S_DIM) sseg[t] = d_seg_start[t];
    #pragma unroll
    for (int i = t; i < P_DIM; i += 128) smeta[i] = d_meta[i];
    __syncthreads();                         // metadata visible to all warps

    // --- wait for bulk-copy completion (parity 0, acquire) -----------------
    {
        uint32_t done;
        asm volatile(
            "{\n\t"
            ".reg .pred p;\n\t"
            "mbarrier.try_wait.parity.acquire.cta.shared::cta.b64 p, [%1], 0;\n\t"
            "selp.b32 %0, 1, 0, p;\n\t"
            "}" : "=r"(done) : "r"(mbar) : "memory");
        if (!done) {
            asm volatile(
                "{\n\t"
                ".reg .pred P1;\n\t"
                "W_%=:\n\t"
                "mbarrier.try_wait.parity.acquire.cta.shared::cta.b64 P1, [%0], 0, 0x989680;\n\t"
                "@P1 bra.uni D_%=;\n\t"
                "bra.uni W_%=;\n\t"
                "D_%=:\n\t"
                "}" :: "r"(mbar) : "memory");
        }
    }

    // --- compute: warp w owns segments w, w+4, ...; thread owns a float4 ---
    float4* o4 = (float4*)(out + (size_t)b * ROW_FLOATS);

    for (int s3 = warp; s3 < S_DIM; s3 += 4) {
        const int beg = sseg[s3];
        const int end = sseg[s3 + 1];
        float4 acc = make_float4(0.f, 0.f, 0.f, 0.f);
        #pragma unroll 2
        for (int j = beg; j < end; j++) {
            const int2  m  = smeta[j];              // LDS.64 broadcast
            const float c  = __int_as_float(m.y);
            const int   i1 = m.x >> 16;             // float4-unit offsets
            const int   i2 = m.x & 0xFFFF;
            const float4 xv = sx4[i1 + lane];       // LDS.128, conflict-free
            const float4 yv = sy4[i2 + lane];
            acc.x = fmaf(c * xv.x, yv.x, acc.x);
            acc.y = fmaf(c * xv.y, yv.y, acc.y);
            acc.z = fmaf(c * xv.z, yv.z, acc.z);
            acc.w = fmaf(c * xv.w, yv.w, acc.w);
        }
        o4[s3 * (E_DIM / 4) + lane] = acc;          // STG.128, coalesced
    }
}

// ---------------------------------------------------------------------------
// Launch wrapper. Inputs (metadata order):
//   0: x_table f32 [N,S*E]  1: y f32 [B,S*E]  2: path_coeff f32 [P]
//   3: x_idx i32 [B]        4: path_idx i32 [P,3]      out: f32 [B,S*E]
// ---------------------------------------------------------------------------
extern "C" void kernel_launch(void* const* d_in, const int* in_sizes, int n_in,
                              void* d_out, int out_size)
{
    const float* x_table    = (const float*)d_in[0];
    const float* y          = (const float*)d_in[1];
    const float* path_coeff = (const float*)d_in[2];
    const int*   x_idx      = (const int*)  d_in[3];
    const int*   path_idx   = (const int*)  d_in[4];
    float*       out        = (float*)d_out;

    (void)in_sizes; (void)n_in; (void)out_size;

    static bool attr_set = false;
    if (!attr_set) {
        cudaFuncSetAttribute(seg_poly_kernel,
                             cudaFuncAttributeMaxDynamicSharedMemorySize,
                             SMEM_BYTES);
        attr_set = true;
    }

    prep_paths_kernel<<<1, P_DIM>>>(path_coeff, path_idx);
    seg_poly_kernel<<<B_DIM, 128, SMEM_BYTES>>>(x_table, y, x_idx, out);
}

// round 7
// speedup vs baseline: 2.1548x; 1.0004x over previous
#include <cuda_runtime.h>
#include <cstdint>
#include <cstddef>

// Problem constants (fixed by the dataset)
#define E_DIM 128
#define S_DIM 64
#define P_DIM 256
#define B_DIM 4096
#define ROW_FLOATS (S_DIM * E_DIM)          // 8192 floats = 32 KB
#define ROW_BYTES  (ROW_FLOATS * 4)

// ---------------------------------------------------------------------------
// Persistent device scratch: paths sorted by output segment i3.
// meta.x = (i1*32)<<16 | (i2*32)   (float4-unit row offsets, each <= 2016)
// meta.y = bitcast(path coefficient)
// ---------------------------------------------------------------------------
__device__ int  d_seg_start[S_DIM + 1];
__device__ int2 d_meta[P_DIM];

// ---------------------------------------------------------------------------
// Prep: deterministic stable counting-sort of 256 paths by i3 (~2 us).
// ---------------------------------------------------------------------------
__global__ void prep_paths_kernel(const float* __restrict__ path_coeff,
                                  const int*   __restrict__ path_idx)
{
    __shared__ int s_i3[P_DIM];
    __shared__ int s_cnt[S_DIM + 1];

    const int t  = threadIdx.x;              // 0..255
    const int i1 = path_idx[t * 3 + 0];
    const int i2 = path_idx[t * 3 + 1];
    const int i3 = path_idx[t * 3 + 2];
    s_i3[t] = i3;
    if (t <= S_DIM) s_cnt[t] = 0;
    __syncthreads();

    atomicAdd(&s_cnt[i3 + 1], 1);
    __syncthreads();

    if (t == 0) {
        int acc = 0;
        #pragma unroll
        for (int i = 0; i <= S_DIM; i++) { acc += s_cnt[i]; s_cnt[i] = acc; }
    }
    __syncthreads();

    if (t <= S_DIM) d_seg_start[t] = s_cnt[t];

    int rank = 0;                            // stable rank within segment
    for (int j = 0; j < t; j++) rank += (s_i3[j] == i3) ? 1 : 0;
    const int pos = s_cnt[i3] + rank;

    d_meta[pos] = make_int2(((i1 * (E_DIM / 4)) << 16) | (i2 * (E_DIM / 4)),
                            __float_as_int(path_coeff[t]));
}

// ---------------------------------------------------------------------------
// Shared-memory layout (dynamic):
//   [0,8)        mbarrier
//   [16,276)     seg_start[65]
//   [280,2328)   meta int2[256]
//   [2432,35200) sx  (32 KB, x-row)
//   [35200,67968) sy (32 KB, y-row)
// ---------------------------------------------------------------------------
#define OFF_MBAR 0
#define OFF_SEG  16
#define OFF_META 280
#define OFF_SX   2432
#define OFF_SY   (OFF_SX + ROW_BYTES)
#define SMEM_BYTES (OFF_SY + ROW_BYTES)

__device__ __forceinline__ uint32_t smem_u32(const void* p) {
    uint32_t a;
    asm("{ .reg .u64 t; cvta.to.shared.u64 t, %1; cvt.u32.u64 %0, t; }"
        : "=r"(a) : "l"(p));
    return a;
}

__global__ __launch_bounds__(128, 3)
void seg_poly_kernel(const float* __restrict__ x_table,
                     const float* __restrict__ y,
                     const int*   __restrict__ x_idx,
                     float*       __restrict__ out)
{
    extern __shared__ char smem[];
    int*          sseg  = (int*)  (smem + OFF_SEG);
    int2*         smeta = (int2*) (smem + OFF_META);
    const float4* sx4   = (const float4*)(smem + OFF_SX);
    const float4* sy4   = (const float4*)(smem + OFF_SY);

    const int b    = blockIdx.x;
    const int t    = threadIdx.x;            // 0..127
    const int warp = t >> 5;
    const int lane = t & 31;

    const uint32_t mbar = smem_u32(smem + OFF_MBAR);

    // --- init mbarrier, then kick off the two 32 KB bulk copies ------------
    if (t == 0) {
        asm volatile("mbarrier.init.shared.b64 [%0], 1;" :: "r"(mbar) : "memory");
    }
    __syncthreads();

    if (t == 0) {
        asm volatile("mbarrier.arrive.expect_tx.shared.b64 _, [%0], %1;"
                     :: "r"(mbar), "r"(2 * ROW_BYTES) : "memory");
        const char* xsrc = (const char*)(x_table + (size_t)x_idx[b] * ROW_FLOATS);
        const char* ysrc = (const char*)(y       + (size_t)b        * ROW_FLOATS);
        asm volatile(
            "cp.async.bulk.shared::cta.global.mbarrier::complete_tx::bytes "
            "[%0], [%1], %2, [%3];"
            :: "r"(smem_u32(smem + OFF_SX)), "l"(xsrc), "r"(ROW_BYTES), "r"(mbar)
            : "memory");
        asm volatile(
            "cp.async.bulk.shared::cta.global.mbarrier::complete_tx::bytes "
            "[%0], [%1], %2, [%3];"
            :: "r"(smem_u32(smem + OFF_SY)), "l"(ysrc), "r"(ROW_BYTES), "r"(mbar)
            : "memory");
    }

    // --- overlap: stage path metadata while bulk copies fly ----------------
    if (t <= S_DIM) sseg[t] = d_seg_start[t];
    #pragma unroll
    for (int i = t; i < P_DIM; i += 128) smeta[i] = d_meta[i];
    __syncthreads();                         // metadata visible to all warps

    // --- wait for bulk-copy completion (parity 0, acquire) -----------------
    {
        uint32_t done;
        asm volatile(
            "{\n\t"
            ".reg .pred p;\n\t"
            "mbarrier.try_wait.parity.acquire.cta.shared::cta.b64 p, [%1], 0;\n\t"
            "selp.b32 %0, 1, 0, p;\n\t"
            "}" : "=r"(done) : "r"(mbar) : "memory");
        if (!done) {
            asm volatile(
                "{\n\t"
                ".reg .pred P1;\n\t"
                "W_%=:\n\t"
                "mbarrier.try_wait.parity.acquire.cta.shared::cta.b64 P1, [%0], 0, 0x989680;\n\t"
                "@P1 bra.uni D_%=;\n\t"
                "bra.uni W_%=;\n\t"
                "D_%=:\n\t"
                "}" :: "r"(mbar) : "memory");
        }
    }

    // --- compute: warp w owns segments w, w+4, ...; thread owns a float4 ---
    float4* o4 = (float4*)(out + (size_t)b * ROW_FLOATS);

    for (int s3 = warp; s3 < S_DIM; s3 += 4) {
        const int beg = sseg[s3];
        const int end = sseg[s3 + 1];
        float4 acc = make_float4(0.f, 0.f, 0.f, 0.f);
        #pragma unroll 2
        for (int j = beg; j < end; j++) {
            const int2  m  = smeta[j];              // LDS.64 broadcast
            const float c  = __int_as_float(m.y);
            const int   i1 = m.x >> 16;             // float4-unit offsets
            const int   i2 = m.x & 0xFFFF;
            const float4 xv = sx4[i1 + lane];       // LDS.128, conflict-free
            const float4 yv = sy4[i2 + lane];
            acc.x = fmaf(c * xv.x, yv.x, acc.x);
            acc.y = fmaf(c * xv.y, yv.y, acc.y);
            acc.z = fmaf(c * xv.z, yv.z, acc.z);
            acc.w = fmaf(c * xv.w, yv.w, acc.w);
        }
        o4[s3 * (E_DIM / 4) + lane] = acc;          // STG.128, coalesced
    }
}

// ---------------------------------------------------------------------------
// Launch wrapper. Inputs (metadata order):
//   0: x_table f32 [N,S*E]  1: y f32 [B,S*E]  2: path_coeff f32 [P]
//   3: x_idx i32 [B]        4: path_idx i32 [P,3]      out: f32 [B,S*E]
// ---------------------------------------------------------------------------
extern "C" void kernel_launch(void* const* d_in, const int* in_sizes, int n_in,
                              void* d_out, int out_size)
{
    const float* x_table    = (const float*)d_in[0];
    const float* y          = (const float*)d_in[1];
    const float* path_coeff = (const float*)d_in[2];
    const int*   x_idx      = (const int*)  d_in[3];
    const int*   path_idx   = (const int*)  d_in[4];
    float*       out        = (float*)d_out;

    (void)in_sizes; (void)n_in; (void)out_size;

    static bool attr_set = false;
    if (!attr_set) {
        cudaFuncSetAttribute(seg_poly_kernel,
                             cudaFuncAttributeMaxDynamicSharedMemorySize,
                             SMEM_BYTES);
        attr_set = true;
    }

    prep_paths_kernel<<<1, P_DIM>>>(path_coeff, path_idx);
    seg_poly_kernel<<<B_DIM, 128, SMEM_BYTES>>>(x_table, y, x_idx, out);
}

// round 8
// speedup vs baseline: 2.2080x; 1.0247x over previous
#include <cuda_runtime.h>
#include <cstdint>
#include <cstddef>

// Problem constants (fixed by the dataset)
#define E_DIM 128
#define S_DIM 64
#define P_DIM 256
#define B_DIM 4096
#define ROW_FLOATS (S_DIM * E_DIM)          // 8192 floats = 32 KB
#define ROW_BYTES  (ROW_FLOATS * 4)
#define N_STAGES   3

// ---------------------------------------------------------------------------
// Shared-memory layout (dynamic, 1024-aligned stage base):
//   [0,24)         mbarrier[3]
//   [32,292)       seg_start[65]
//   [304,2352)     meta int2[256]          (sorted by i3)
//   [2352,3376)    prep scratch s_i3[256]
//   [3376,3640)    prep scratch s_cnt[65]
//   [4096 + st*65536) : stage st = [sx 32KB][sy 32KB]
// ---------------------------------------------------------------------------
#define OFF_MBAR   0
#define OFF_SEG    32
#define OFF_META   304
#define OFF_I3     2352
#define OFF_CNT    3376
#define OFF_STAGE  4096
#define STAGE_BYTES (2 * ROW_BYTES)
#define SMEM_BYTES (OFF_STAGE + N_STAGES * STAGE_BYTES)   // 200704

__device__ __forceinline__ uint32_t smem_u32(const void* p) {
    uint32_t a;
    asm("{ .reg .u64 t; cvta.to.shared.u64 t, %1; cvt.u32.u64 %0, t; }"
        : "=r"(a) : "l"(p));
    return a;
}

__device__ __forceinline__ void mbar_wait(uint32_t mbar, uint32_t parity) {
    uint32_t done;
    asm volatile(
        "{\n\t"
        ".reg .pred p;\n\t"
        "mbarrier.try_wait.parity.acquire.cta.shared::cta.b64 p, [%1], %2;\n\t"
        "selp.b32 %0, 1, 0, p;\n\t"
        "}" : "=r"(done) : "r"(mbar), "r"(parity) : "memory");
    if (!done) {
        asm volatile(
            "{\n\t"
            ".reg .pred P1;\n\t"
            "W_%=:\n\t"
            "mbarrier.try_wait.parity.acquire.cta.shared::cta.b64 P1, [%0], %1, 0x989680;\n\t"
            "@P1 bra.uni D_%=;\n\t"
            "bra.uni W_%=;\n\t"
            "D_%=:\n\t"
            "}" :: "r"(mbar), "r"(parity) : "memory");
    }
}

__global__ __launch_bounds__(256, 1)
void seg_poly_kernel(const float* __restrict__ x_table,
                     const float* __restrict__ y,
                     const int*   __restrict__ x_idx,
                     float*       __restrict__ out)
{
    extern __shared__ char smem[];
    int*  sseg  = (int*) (smem + OFF_SEG);
    int2* smeta = (int2*)(smem + OFF_META);
    int*  s_i3  = (int*) (smem + OFF_I3);
    int*  s_cnt = (int*) (smem + OFF_CNT);

    const int t    = threadIdx.x;            // 0..255
    const int warp = t >> 5;                 // 0..7
    const int lane = t & 31;
    const int G    = gridDim.x;

    const uint32_t mbar0 = smem_u32(smem + OFF_MBAR);

    // --- init the 3 mbarriers ---------------------------------------------
    if (t < N_STAGES) {
        asm volatile("mbarrier.init.shared.b64 [%0], 1;"
                     :: "r"(mbar0 + 8u * t) : "memory");
    }
    if (t <= S_DIM) s_cnt[t] = 0;
    __syncthreads();

    // --- prologue: issue bulk copies for first two rows of this CTA --------
    const int r0 = blockIdx.x;
    if (t == 0) {
        #pragma unroll
        for (int u = 0; u < 2; u++) {
            const int r = r0 + u * G;
            if (r < B_DIM) {
                const uint32_t mb = mbar0 + 8u * u;
                asm volatile("mbarrier.arrive.expect_tx.shared.b64 _, [%0], %1;"
                             :: "r"(mb), "r"(STAGE_BYTES) : "memory");
                const uint32_t dst = smem_u32(smem + OFF_STAGE) + u * STAGE_BYTES;
                const char* xsrc = (const char*)(x_table + (size_t)x_idx[r] * ROW_FLOATS);
                const char* ysrc = (const char*)(y + (size_t)r * ROW_FLOATS);
                asm volatile(
                    "cp.async.bulk.shared::cta.global.mbarrier::complete_tx::bytes "
                    "[%0], [%1], %2, [%3];"
                    :: "r"(dst), "l"(xsrc), "r"(ROW_BYTES), "r"(mb) : "memory");
                asm volatile(
                    "cp.async.bulk.shared::cta.global.mbarrier::complete_tx::bytes "
                    "[%0], [%1], %2, [%3];"
                    :: "r"(dst + ROW_BYTES), "l"(ysrc), "r"(ROW_BYTES), "r"(mb) : "memory");
            }
        }
    }

    // --- inline prep (overlapped with prologue copies) ---------------------
    // Deterministic stable counting-sort of the 256 paths by i3.
    {
        const float* path_coeff = (const float*)0;  // set below via params trick
        (void)path_coeff;
    }
    // path inputs passed through globals-free route: re-read from params
    // (x_table..out are the only params; path data comes via constant pointers
    //  stored in __device__ globals set by a tiny setup kernel-free trick is
    //  not needed: we pass them as extra kernel params instead)
    // -- see kernel signature extension below --
    // (placeholder removed; actual prep below uses pc/pi params)
    __syncthreads();   // ensure s_cnt zeros visible (prep continues in main body)

    // NOTE: prep body lives in seg_poly_main below; this kernel is replaced.
}

// ---------------------------------------------------------------------------
// Actual kernel (with path params). The stub above is unused; kept minimal.
// ---------------------------------------------------------------------------
__global__ __launch_bounds__(256, 1)
void seg_poly_main(const float* __restrict__ x_table,
                   const float* __restrict__ y,
                   const int*   __restrict__ x_idx,
                   const float* __restrict__ path_coeff,
                   const int*   __restrict__ path_idx,
                   float*       __restrict__ out)
{
    extern __shared__ char smem[];
    int*  sseg  = (int*) (smem + OFF_SEG);
    int2* smeta = (int2*)(smem + OFF_META);
    int*  s_i3  = (int*) (smem + OFF_I3);
    int*  s_cnt = (int*) (smem + OFF_CNT);

    const int t    = threadIdx.x;            // 0..255
    const int warp = t >> 5;                 // 0..7
    const int lane = t & 31;
    const int G    = gridDim.x;

    const uint32_t mbar0 = smem_u32(smem + OFF_MBAR);

    if (t < N_STAGES) {
        asm volatile("mbarrier.init.shared.b64 [%0], 1;"
                     :: "r"(mbar0 + 8u * t) : "memory");
    }
    if (t <= S_DIM) s_cnt[t] = 0;
    __syncthreads();

    // --- prologue: bulk copies for this CTA's first two rows ---------------
    const int r0 = blockIdx.x;
    if (t == 0) {
        #pragma unroll
        for (int u = 0; u < 2; u++) {
            const int r = r0 + u * G;
            if (r < B_DIM) {
                const uint32_t mb = mbar0 + 8u * u;
                asm volatile("mbarrier.arrive.expect_tx.shared.b64 _, [%0], %1;"
                             :: "r"(mb), "r"(STAGE_BYTES) : "memory");
                const uint32_t dst = smem_u32(smem + OFF_STAGE) + u * STAGE_BYTES;
                const char* xsrc = (const char*)(x_table + (size_t)x_idx[r] * ROW_FLOATS);
                const char* ysrc = (const char*)(y + (size_t)r * ROW_FLOATS);
                asm volatile(
                    "cp.async.bulk.shared::cta.global.mbarrier::complete_tx::bytes "
                    "[%0], [%1], %2, [%3];"
                    :: "r"(dst), "l"(xsrc), "r"(ROW_BYTES), "r"(mb) : "memory");
                asm volatile(
                    "cp.async.bulk.shared::cta.global.mbarrier::complete_tx::bytes "
                    "[%0], [%1], %2, [%3];"
                    :: "r"(dst + ROW_BYTES), "l"(ysrc), "r"(ROW_BYTES), "r"(mb) : "memory");
            }
        }
    }

    // --- inline prep: stable counting-sort of 256 paths by i3 --------------
    {
        const int i1 = path_idx[t * 3 + 0];
        const int i2 = path_idx[t * 3 + 1];
        const int i3 = path_idx[t * 3 + 2];
        s_i3[t] = i3;
        __syncthreads();
        atomicAdd(&s_cnt[i3 + 1], 1);
        __syncthreads();
        if (t == 0) {
            int acc = 0;
            #pragma unroll
            for (int i = 0; i <= S_DIM; i++) { acc += s_cnt[i]; s_cnt[i] = acc; }
        }
        __syncthreads();
        if (t <= S_DIM) sseg[t] = s_cnt[t];
        int rank = 0;                        // stable rank within segment
        for (int j = 0; j < t; j++) rank += (s_i3[j] == i3) ? 1 : 0;
        smeta[s_cnt[i3] + rank] =
            make_int2(((i1 * (E_DIM / 4)) << 16) | (i2 * (E_DIM / 4)),
                      __float_as_int(path_coeff[t]));
    }
    __syncthreads();

    // --- main pipelined loop over this CTA's rows --------------------------
    int k = 0;
    for (int r = r0; r < B_DIM; r += G, k++) {
        const int st = k % N_STAGES;
        const int u  = k / N_STAGES;         // use-count of this stage

        // issue copy for row r + 2G into stage (k+2)%3 (freed 1 iter ago)
        const int rpre = r + 2 * G;
        if (t == 0 && rpre < B_DIM) {
            const int st2 = (k + 2) % N_STAGES;
            const uint32_t mb = mbar0 + 8u * st2;
            asm volatile("mbarrier.arrive.expect_tx.shared.b64 _, [%0], %1;"
                         :: "r"(mb), "r"(STAGE_BYTES) : "memory");
            const uint32_t dst = smem_u32(smem + OFF_STAGE) + st2 * STAGE_BYTES;
            const char* xsrc = (const char*)(x_table + (size_t)x_idx[rpre] * ROW_FLOATS);
            const char* ysrc = (const char*)(y + (size_t)rpre * ROW_FLOATS);
            asm volatile(
                "cp.async.bulk.shared::cta.global.mbarrier::complete_tx::bytes "
                "[%0], [%1], %2, [%3];"
                :: "r"(dst), "l"(xsrc), "r"(ROW_BYTES), "r"(mb) : "memory");
            asm volatile(
                "cp.async.bulk.shared::cta.global.mbarrier::complete_tx::bytes "
                "[%0], [%1], %2, [%3];"
                :: "r"(dst + ROW_BYTES), "l"(ysrc), "r"(ROW_BYTES), "r"(mb) : "memory");
        }

        // wait for this row's data
        mbar_wait(mbar0 + 8u * st, u & 1);

        const float4* sx4 = (const float4*)(smem + OFF_STAGE + st * STAGE_BYTES);
        const float4* sy4 = sx4 + (ROW_FLOATS / 4);
        float4* o4 = (float4*)(out + (size_t)r * ROW_FLOATS);

        // warp w owns segments w, w+8, ... ; thread owns one float4 of E
        for (int s3 = warp; s3 < S_DIM; s3 += 8) {
            const int beg = sseg[s3];
            const int end = sseg[s3 + 1];
            float4 acc = make_float4(0.f, 0.f, 0.f, 0.f);
            #pragma unroll 2
            for (int j = beg; j < end; j++) {
                const int2  m  = smeta[j];          // LDS.64 broadcast
                const float c  = __int_as_float(m.y);
                const int   i1 = m.x >> 16;         // float4-unit offsets
                const int   i2 = m.x & 0xFFFF;
                const float4 xv = sx4[i1 + lane];   // LDS.128, conflict-free
                const float4 yv = sy4[i2 + lane];
                acc.x = fmaf(c * xv.x, yv.x, acc.x);
                acc.y = fmaf(c * xv.y, yv.y, acc.y);
                acc.z = fmaf(c * xv.z, yv.z, acc.z);
                acc.w = fmaf(c * xv.w, yv.w, acc.w);
            }
            o4[s3 * (E_DIM / 4) + lane] = acc;      // STG.128, coalesced
        }

        __syncthreads();    // all warps done with stage st before reuse
    }
}

// ---------------------------------------------------------------------------
// Launch wrapper. Inputs (metadata order):
//   0: x_table f32 [N,S*E]  1: y f32 [B,S*E]  2: path_coeff f32 [P]
//   3: x_idx i32 [B]        4: path_idx i32 [P,3]      out: f32 [B,S*E]
// ---------------------------------------------------------------------------
extern "C" void kernel_launch(void* const* d_in, const int* in_sizes, int n_in,
                              void* d_out, int out_size)
{
    const float* x_table    = (const float*)d_in[0];
    const float* y          = (const float*)d_in[1];
    const float* path_coeff = (const float*)d_in[2];
    const int*   x_idx      = (const int*)  d_in[3];
    const int*   path_idx   = (const int*)  d_in[4];
    float*       out        = (float*)d_out;

    (void)in_sizes; (void)n_in; (void)out_size;

    static int sm_count = 0;
    if (sm_count == 0) {
        cudaDeviceGetAttribute(&sm_count, cudaDevAttrMultiProcessorCount, 0);
        if (sm_count <= 0) sm_count = 148;
        cudaFuncSetAttribute(seg_poly_main,
                             cudaFuncAttributeMaxDynamicSharedMemorySize,
                             SMEM_BYTES);
    }

    seg_poly_main<<<sm_count, 256, SMEM_BYTES>>>(
        x_table, y, x_idx, path_coeff, path_idx, out);
}